// round 7
// baseline (speedup 1.0000x reference)
#include <cuda_runtime.h>
#include <cstdint>

// ---------------------------------------------------------------------------
// DualOrthogonalAttention fused kernel, round 7: 3xTF32 warp-MMA (m16n8k8).
// Same structure as round 6, but value-path GEMMs use split-precision
// tf32 (hi/lo decomposition, 3 MMAs) -> ~fp32 accuracy. Loss gram stays
// single-pass tf32 with RNA rounding.
// ---------------------------------------------------------------------------

#define BSZ 1024
#define S 62
#define DIM 65
#define H 10
#define NT 512

#define SA 76
#define SB 72
#define SW 76
#define WBUF_SZ (72*SW)

#define OFF_FN76 0
#define OFF_FR76 (OFF_FN76 + 64*SA)
#define OFF_FN72 (OFF_FR76 + 64*SA)
#define OFF_FR72 (OFF_FN72 + 64*SB)
#define OFF_Q    (OFF_FR72 + 64*SB)
#define OFF_K    (OFF_Q + 64*SA)
#define OFF_A1   (OFF_K + 64*SA)
#define OFF_A2   (OFF_A1 + 64*SA)
#define OFF_W    (OFF_A2 + 64*SA)
#define OFF_BIAS (OFF_W + 3*WBUF_SZ)
#define OFF_G1   (OFF_BIAS + 3*72)
#define OFF_G2   (OFF_G1 + 72)
#define OFF_MEAN (OFF_G2 + 72)
#define OFF_WARP (OFF_MEAN + 132)
#define SMEM_FLOATS (OFF_WARP + 20)   // 55328 floats = 216.1 KB

__device__ float g_norms[BSZ * H];

// ---------------------------------------------------------------------------
__device__ __forceinline__ void cp_async4(uint32_t dst, const float* src) {
    asm volatile("cp.async.ca.shared.global [%0], [%1], 4;\n" :: "r"(dst), "l"(src));
}
__device__ __forceinline__ void cp_commit() {
    asm volatile("cp.async.commit_group;\n" ::);
}
__device__ __forceinline__ void cp_wait0() {
    asm volatile("cp.async.wait_group 0;\n" ::);
}

__device__ __forceinline__ void prefetch_wb(const float* __restrict__ gW,
                                            const float* __restrict__ gb,
                                            float* sW, float* sB) {
    uint32_t wbase = (uint32_t)__cvta_generic_to_shared(sW);
    for (int idx = threadIdx.x; idx < DIM * DIM; idx += NT) {
        const int row = idx / DIM;
        const int col = idx - row * DIM;
        cp_async4(wbase + (uint32_t)(row * SW + col) * 4u, gW + idx);
    }
    if (threadIdx.x < DIM) {
        uint32_t bbase = (uint32_t)__cvta_generic_to_shared(sB);
        cp_async4(bbase + threadIdx.x * 4u, gb + threadIdx.x);
    }
    cp_commit();
}

// ---------------------------------------------------------------------------
__device__ __forceinline__ uint32_t f2tf32(float x) {
    uint32_t r;
    asm("cvt.rna.tf32.f32 %0, %1;\n" : "=r"(r) : "f"(x));
    return r;
}

__device__ __forceinline__ void mma8(float* c, uint32_t a0, uint32_t a1,
                                     uint32_t a2, uint32_t a3,
                                     uint32_t b0, uint32_t b1) {
    asm volatile(
        "mma.sync.aligned.m16n8k8.row.col.f32.tf32.tf32.f32 "
        "{%0,%1,%2,%3}, {%4,%5,%6,%7}, {%8,%9}, {%0,%1,%2,%3};\n"
        : "+f"(c[0]), "+f"(c[1]), "+f"(c[2]), "+f"(c[3])
        : "r"(a0), "r"(a1), "r"(a2), "r"(a3), "r"(b0), "r"(b1));
}

// ---------------------------------------------------------------------------
// Warp tile: rows [mt*16, +16), cols [n0, n0+8*NS). C = A(row-major, SA) x B.
// BT: B element (k,n) at B[n*SA + k]; !BT: B[k*SB + n].
// PREC: 3xTF32 split (hi/lo); else single-pass RNA tf32.
// EPI 0: smem C (stride SA) += bias[col]      EPI 1: smem C (stride SB) *= scale
// EPI 2: gmem C[r*65+col] = aux[col]*acc      EPI 3: return sum (acc - I)^2
// ---------------------------------------------------------------------------
template <int EPI, bool BT, int NS, int KS, bool PREC>
__device__ __forceinline__ float mma_tile(
    const float* __restrict__ A, const float* __restrict__ B,
    const int mt, const int n0,
    float* __restrict__ C, const float* __restrict__ aux, const float scale)
{
    const int lane = threadIdx.x & 31;
    const int lr = lane >> 2;
    const int lc = lane & 3;

    float acc[NS][4];
#pragma unroll
    for (int ns = 0; ns < NS; ns++) {
        acc[ns][0] = 0.f; acc[ns][1] = 0.f; acc[ns][2] = 0.f; acc[ns][3] = 0.f;
    }

    const float* Ap = A + (mt * 16 + lr) * SA + lc;
    const float* Bp = BT ? (B + lr * SA + lc) : (B + lc * SB + lr);

#pragma unroll
    for (int ks = 0; ks < KS; ks++) {
        const int k8 = ks * 8;
        float af[4];
        af[0] = Ap[k8];
        af[1] = Ap[8 * SA + k8];
        af[2] = Ap[k8 + 4];
        af[3] = Ap[8 * SA + k8 + 4];
        uint32_t ahi[4], alo[4];
#pragma unroll
        for (int i = 0; i < 4; i++) {
            ahi[i] = f2tf32(af[i]);
            if (PREC) alo[i] = f2tf32(af[i] - __uint_as_float(ahi[i]));
        }
#pragma unroll
        for (int ns = 0; ns < NS; ns++) {
            const int n = n0 + ns * 8;
            float bf0, bf1;
            if (BT) {
                bf0 = Bp[n * SA + k8];
                bf1 = Bp[n * SA + k8 + 4];
            } else {
                bf0 = Bp[k8 * SB + n];
                bf1 = Bp[(k8 + 4) * SB + n];
            }
            const uint32_t bhi0 = f2tf32(bf0);
            const uint32_t bhi1 = f2tf32(bf1);
            mma8(acc[ns], ahi[0], ahi[1], ahi[2], ahi[3], bhi0, bhi1);
            if (PREC) {
                const uint32_t blo0 = f2tf32(bf0 - __uint_as_float(bhi0));
                const uint32_t blo1 = f2tf32(bf1 - __uint_as_float(bhi1));
                mma8(acc[ns], alo[0], alo[1], alo[2], alo[3], bhi0, bhi1);
                mma8(acc[ns], ahi[0], ahi[1], ahi[2], ahi[3], blo0, blo1);
            }
        }
    }

    float ss = 0.f;
    const int r0 = mt * 16 + lr;       // < 62 always (max 55)
    const int rr = r0 + 8;             // up to 63

#pragma unroll
    for (int ns = 0; ns < NS; ns++) {
        const int col = n0 + ns * 8 + 2 * lc;
        if (EPI == 0) {
            const float b0v = aux[col], b1v = aux[col + 1];
            *(float2*)(C + r0 * SA + col) = make_float2(acc[ns][0] + b0v, acc[ns][1] + b1v);
            *(float2*)(C + rr * SA + col) = make_float2(acc[ns][2] + b0v, acc[ns][3] + b1v);
        } else if (EPI == 1) {
            *(float2*)(C + r0 * SB + col) = make_float2(acc[ns][0] * scale, acc[ns][1] * scale);
            *(float2*)(C + rr * SB + col) = make_float2(acc[ns][2] * scale, acc[ns][3] * scale);
        } else if (EPI == 2) {
            if (col < 64) {
                const float g0 = aux[col], g1 = aux[col + 1];
                C[r0 * DIM + col]     = g0 * acc[ns][0];
                C[r0 * DIM + col + 1] = g1 * acc[ns][1];
                if (rr < S) {
                    C[rr * DIM + col]     = g0 * acc[ns][2];
                    C[rr * DIM + col + 1] = g1 * acc[ns][3];
                }
            } else if (col == 64) {
                const float g0 = aux[64];
                C[r0 * DIM + 64] = g0 * acc[ns][0];
                if (rr < S) C[rr * DIM + 64] = g0 * acc[ns][2];
            }
        } else {  // EPI 3: loss
            if (col < S) {
                const float d = acc[ns][0] - ((r0 == col) ? 1.f : 0.f);
                ss = fmaf(d, d, ss);
            }
            if (col + 1 < S) {
                const float d = acc[ns][1] - ((r0 == col + 1) ? 1.f : 0.f);
                ss = fmaf(d, d, ss);
            }
            if (rr < S) {
                if (col < S) {
                    const float d = acc[ns][2] - ((rr == col) ? 1.f : 0.f);
                    ss = fmaf(d, d, ss);
                }
                if (col + 1 < S) {
                    const float d = acc[ns][3] - ((rr == col + 1) ? 1.f : 0.f);
                    ss = fmaf(d, d, ss);
                }
            }
        }
    }
    return ss;
}

// row softmax over sS [62 x SB]; writes A (stride SA), zeroing cols 62,63
__device__ __forceinline__ void softmax62(const float* __restrict__ sS_,
                                          float* __restrict__ A) {
    const int warp = threadIdx.x >> 5;
    const int lane = threadIdx.x & 31;
    const bool ok1 = (lane + 32) < S;
    for (int r = warp; r < S; r += 16) {
        const float* row = sS_ + r * SB;
        const float v0 = row[lane];
        const float v1 = ok1 ? row[lane + 32] : -1e30f;
        float m = fmaxf(v0, v1);
#pragma unroll
        for (int off = 16; off; off >>= 1) m = fmaxf(m, __shfl_xor_sync(0xffffffffu, m, off));
        const float e0 = __expf(v0 - m);
        const float e1 = ok1 ? __expf(v1 - m) : 0.f;
        float s = e0 + e1;
#pragma unroll
        for (int off = 16; off; off >>= 1) s += __shfl_xor_sync(0xffffffffu, s, off);
        const float inv = 1.0f / s;
        A[r * SA + lane] = e0 * inv;
        A[r * SA + lane + 32] = ok1 ? (e1 * inv) : 0.f;
    }
}

__global__ void __launch_bounds__(NT, 1)
fused_kernel(const float* __restrict__ Fn, const float* __restrict__ Fr,
             const float* __restrict__ Wq1, const float* __restrict__ bq1,
             const float* __restrict__ Wk1, const float* __restrict__ bk1,
             const float* __restrict__ Wq2, const float* __restrict__ bq2,
             const float* __restrict__ Wk2, const float* __restrict__ bk2,
             const float* __restrict__ Wg, const float* __restrict__ bg,
             float* __restrict__ out)
{
    extern __shared__ float sm[];
    const int tid = threadIdx.x;
    const int b = blockIdx.x;
    const int w = tid >> 5;

    float* sFn76 = sm + OFF_FN76;
    float* sFr76 = sm + OFF_FR76;
    float* sFn72 = sm + OFF_FN72;
    float* sFr72 = sm + OFF_FR72;
    float* sQ    = sm + OFF_Q;
    float* sK    = sm + OFF_K;
    float* sA1   = sm + OFF_A1;
    float* sA2   = sm + OFF_A2;
    float* sWp   = sm + OFF_W;
    float* sBs   = sm + OFF_BIAS;
    float* sG1   = sm + OFF_G1;
    float* sG2   = sm + OFF_G2;
    float* smean = sm + OFF_MEAN;
    float* swarp = sm + OFF_WARP;

    // zero everything once: all K/M pads become hard zeros
    {
        float4* z = (float4*)sm;
        const float4 z4 = make_float4(0.f, 0.f, 0.f, 0.f);
        for (int i = tid; i < SMEM_FLOATS / 4; i += NT) z[i] = z4;
    }
    __syncthreads();

    prefetch_wb(Wq1, bq1, sWp + 0 * WBUF_SZ, sBs + 0 * 72);
    prefetch_wb(Wk1, bk1, sWp + 1 * WBUF_SZ, sBs + 1 * 72);

    for (int idx = tid; idx < S * DIM; idx += NT) {
        const int i = idx / DIM;
        const int d = idx - i * DIM;
        const float vn = Fn[(size_t)b * S * DIM + idx];
        const float vr = Fr[(size_t)b * S * DIM + idx];
        sFn76[i * SA + d] = vn;
        sFn72[i * SB + d] = vn;
        sFr76[i * SA + d] = vr;
        sFr72[i * SB + d] = vr;
    }
    __syncthreads();

    // gate
    if (tid < 2 * DIM) {
        const int d = (tid < DIM) ? tid : tid - DIM;
        const float* src = (tid < DIM) ? sFn76 : sFr76;
        float s = 0.f;
        for (int i = 0; i < S; i++) s += src[i * SA + d];
        smean[tid] = s * (1.0f / (float)S);
    }
    __syncthreads();
    if (tid < DIM) {
        float acc = bg[tid];
        const float* wr = Wg + tid * 2 * DIM;
#pragma unroll 10
        for (int c = 0; c < 2 * DIM; c++) acc = fmaf(wr[c], smean[c], acc);
        const float g = 1.0f / (1.0f + __expf(-acc));
        sG1[tid] = g;
        sG2[tid] = 1.0f - g;
    }

    const float scale = rsqrtf((float)DIM);
    const int mt = w >> 2;
    const int gq = w & 3;
    const int gw = (w + mt) & 3;

    for (int h = 0; h < H; h++) {
        const int woff = h * DIM * DIM;
        const int boff = h * DIM;
        const int d1a = (4 * h) % 3, d1b = (4 * h + 1) % 3;
        const int d2a = (4 * h + 2) % 3, d2b = (4 * h + 3) % 3;
        float* sS = sWp + d1b * WBUF_SZ;
        float* o1 = out + ((size_t)(b * H + h) * 124) * DIM;
        float* o2 = o1 + (size_t)S * DIM;

        // S1: dir1 weights ready
        cp_wait0();
        __syncthreads();

        // S2: dir1 projections
        {
            const float* wq = sWp + d1a * WBUF_SZ;
            const float* wk = sWp + d1b * WBUF_SZ;
            const float* bq = sBs + d1a * 72;
            const float* bk = sBs + d1b * 72;
            if (gw < 3) {
                mma_tile<0, true, 2, 9, true>(sFn76, wq, mt, gw * 16, sQ, bq, 0.f);
                mma_tile<0, true, 2, 9, true>(sFr76, wk, mt, gw * 16, sK, bk, 0.f);
            } else {
                mma_tile<0, true, 3, 9, true>(sFn76, wq, mt, 48, sQ, bq, 0.f);
                mma_tile<0, true, 3, 9, true>(sFr76, wk, mt, 48, sK, bk, 0.f);
            }
        }
        __syncthreads();

        // S3: prefetch dir2 weights; logits1
        prefetch_wb(Wq2 + woff, bq2 + boff, sWp + d2a * WBUF_SZ, sBs + d2a * 72);
        prefetch_wb(Wk2 + woff, bk2 + boff, sWp + d2b * WBUF_SZ, sBs + d2b * 72);
        mma_tile<1, true, 2, 9, true>(sQ, sK, mt, gq * 16, sS, 0, scale);
        __syncthreads();

        // S4: softmax1 -> A1
        softmax62(sS, sA1);

        // S5: dir2 weights ready; dir2 projections
        cp_wait0();
        __syncthreads();
        {
            const float* wq = sWp + d2a * WBUF_SZ;
            const float* wk = sWp + d2b * WBUF_SZ;
            const float* bq = sBs + d2a * 72;
            const float* bk = sBs + d2b * 72;
            if (gw < 3) {
                mma_tile<0, true, 2, 9, true>(sFr76, wq, mt, gw * 16, sQ, bq, 0.f);
                mma_tile<0, true, 2, 9, true>(sFn76, wk, mt, gw * 16, sK, bk, 0.f);
            } else {
                mma_tile<0, true, 3, 9, true>(sFr76, wq, mt, 48, sQ, bq, 0.f);
                mma_tile<0, true, 3, 9, true>(sFn76, wk, mt, 48, sK, bk, 0.f);
            }
        }
        __syncthreads();

        // S6: logits2
        mma_tile<1, true, 2, 9, true>(sQ, sK, mt, gq * 16, sS, 0, scale);
        __syncthreads();

        // S7: softmax2 -> A2
        softmax62(sS, sA2);
        __syncthreads();

        // S8: prefetch next dir1; loss gram (single-pass); gated outputs (3x)
        if (h + 1 < H) {
            prefetch_wb(Wq1 + woff + DIM * DIM, bq1 + boff + DIM,
                        sWp + ((4 * h + 4) % 3) * WBUF_SZ, sBs + ((4 * h + 4) % 3) * 72);
            prefetch_wb(Wk1 + woff + DIM * DIM, bk1 + boff + DIM,
                        sWp + ((4 * h + 5) % 3) * WBUF_SZ, sBs + ((4 * h + 5) % 3) * 72);
        }
        float ss = mma_tile<3, true, 2, 8, false>(sA1, sA2, mt, gq * 16, (float*)0, 0, 0.f);
        if (gw < 3) {
            mma_tile<2, false, 2, 8, true>(sA1, sFr72, mt, gw * 16, o1, sG1, 0.f);
            mma_tile<2, false, 2, 8, true>(sA2, sFn72, mt, gw * 16, o2, sG2, 0.f);
        } else {
            mma_tile<2, false, 3, 8, true>(sA1, sFr72, mt, 48, o1, sG1, 0.f);
            mma_tile<2, false, 3, 8, true>(sA2, sFn72, mt, 48, o2, sG2, 0.f);
        }
#pragma unroll
        for (int off = 16; off; off >>= 1) ss += __shfl_xor_sync(0xffffffffu, ss, off);
        if ((tid & 31) == 0) swarp[w] = ss;
        __syncthreads();
        if (tid == 0) {
            float t = 0.f;
#pragma unroll
            for (int ww = 0; ww < 16; ww++) t += swarp[ww];
            g_norms[b * H + h] = sqrtf(t);
        }
    }
}

__global__ void loss_kernel(float* __restrict__ out_loss)
{
    __shared__ float ws[8];
    const int tid = threadIdx.x;
    float s = 0.f;
    for (int i = tid; i < BSZ * H; i += 256) s += g_norms[i];
#pragma unroll
    for (int off = 16; off; off >>= 1) s += __shfl_xor_sync(0xffffffffu, s, off);
    if ((tid & 31) == 0) ws[tid >> 5] = s;
    __syncthreads();
    if (tid == 0) {
        float t = 0.f;
#pragma unroll
        for (int w = 0; w < 8; w++) t += ws[w];
        *out_loss = t / (float)(BSZ * H);
    }
}

extern "C" void kernel_launch(void* const* d_in, const int* in_sizes, int n_in,
                              void* d_out, int out_size)
{
    const float* Fn  = (const float*)d_in[0];
    const float* Fr  = (const float*)d_in[1];
    const float* Wq1 = (const float*)d_in[2];
    const float* bq1 = (const float*)d_in[3];
    const float* Wk1 = (const float*)d_in[4];
    const float* bk1 = (const float*)d_in[5];
    const float* Wq2 = (const float*)d_in[6];
    const float* bq2 = (const float*)d_in[7];
    const float* Wk2 = (const float*)d_in[8];
    const float* bk2 = (const float*)d_in[9];
    const float* Wg  = (const float*)d_in[10];
    const float* bg  = (const float*)d_in[11];
    float* out = (float*)d_out;

    const int smem_bytes = SMEM_FLOATS * (int)sizeof(float);
    cudaFuncSetAttribute(fused_kernel, cudaFuncAttributeMaxDynamicSharedMemorySize, smem_bytes);
    fused_kernel<<<BSZ, NT, smem_bytes>>>(Fn, Fr, Wq1, bq1, Wk1, bk1,
                                          Wq2, bq2, Wk2, bk2, Wg, bg, out);
    loss_kernel<<<1, 256>>>(out + (size_t)out_size - 1);
}